// round 1
// baseline (speedup 1.0000x reference)
#include <cuda_runtime.h>
#include <cuda_bf16.h>
#include <cstddef>

#define BB   2
#define SS   1024
#define LL   2
#define HH   8
#define DD   512
#define DFF  2048
#define DKH  64
#define NTOK (BB*SS)      // 2048
#define NC   (SS/64)      // 16 chunks of 64
#define BH   (BB*HH)      // 16
#define EPSF 1e-5f

// ---------------- scratch (device globals; no allocation) ----------------
__device__ __align__(128) float g_x  [NTOK*DD];
__device__ __align__(128) float g_q  [NTOK*DD];
__device__ __align__(128) float g_k  [NTOK*DD];
__device__ __align__(128) float g_v  [NTOK*DD];
__device__ __align__(128) float g_att[NTOK*DD];
__device__ __align__(128) float g_tmp[NTOK*DD];
__device__ __align__(128) float g_ff [NTOK*DFF];
__device__ __align__(128) float g_kvc[BH*NC*DKH*DKH];
__device__ __align__(128) float g_st [BH*NC*DKH*DKH];

// ---------------- tiled SGEMM: C[M,N] = A[M,K] @ W[K,N] + bias (+epilogue) ----
// EPI: 0 = bias only, 1 = bias + relu, 2 = bias + residual R
template<int EPI>
__global__ void sgemm_kernel(const float* __restrict__ A, const float* __restrict__ W,
                             const float* __restrict__ bias, const float* __restrict__ R,
                             float* __restrict__ C, int M, int N, int K)
{
    __shared__ float As[16][68];
    __shared__ float Bs[16][68];
    const int tid  = threadIdx.x;
    const int tx   = tid & 15, ty = tid >> 4;
    const int brow = blockIdx.y * 64, bcol = blockIdx.x * 64;

    const int arow = tid >> 2,  acol = (tid & 3) * 4;   // A: 64 rows x 16 cols
    const int brw  = tid >> 4,  bcw  = (tid & 15) * 4;  // B: 16 rows x 64 cols

    float acc[4][4] = {};
    const float* Aptr = A + (size_t)(brow + arow) * K + acol;
    const float* Bptr = W + (size_t)brw * N + bcol + bcw;

    for (int k0 = 0; k0 < K; k0 += 16) {
        float4 av = *(const float4*)(Aptr + k0);
        As[acol + 0][arow] = av.x;
        As[acol + 1][arow] = av.y;
        As[acol + 2][arow] = av.z;
        As[acol + 3][arow] = av.w;
        float4 bv = *(const float4*)(Bptr + (size_t)k0 * N);
        *(float4*)&Bs[brw][bcw] = bv;
        __syncthreads();
#pragma unroll
        for (int k = 0; k < 16; ++k) {
            float a0 = As[k][ty*4+0], a1 = As[k][ty*4+1];
            float a2 = As[k][ty*4+2], a3 = As[k][ty*4+3];
            float b0 = Bs[k][tx*4+0], b1 = Bs[k][tx*4+1];
            float b2 = Bs[k][tx*4+2], b3 = Bs[k][tx*4+3];
            acc[0][0] += a0*b0; acc[0][1] += a0*b1; acc[0][2] += a0*b2; acc[0][3] += a0*b3;
            acc[1][0] += a1*b0; acc[1][1] += a1*b1; acc[1][2] += a1*b2; acc[1][3] += a1*b3;
            acc[2][0] += a2*b0; acc[2][1] += a2*b1; acc[2][2] += a2*b2; acc[2][3] += a2*b3;
            acc[3][0] += a3*b0; acc[3][1] += a3*b1; acc[3][2] += a3*b2; acc[3][3] += a3*b3;
        }
        __syncthreads();
    }

#pragma unroll
    for (int ii = 0; ii < 4; ++ii) {
        const int row = brow + ty*4 + ii;
#pragma unroll
        for (int jj = 0; jj < 4; ++jj) {
            const int col = bcol + tx*4 + jj;
            float v = acc[ii][jj] + bias[col];
            if (EPI == 1) v = fmaxf(v, 0.f);
            if (EPI == 2) v += R[(size_t)row * N + col];
            C[(size_t)row * N + col] = v;
        }
    }
}

// ---------------- LayerNorm over last dim (D=512), one block per row -------
__global__ void ln_kernel(const float* __restrict__ X, const float* __restrict__ g,
                          const float* __restrict__ b, float* __restrict__ Y)
{
    const int row = blockIdx.x;
    const int tid = threadIdx.x;
    const float* x = X + (size_t)row * DD;
    __shared__ float rs[256], rs2[256];
    float s = 0.f, s2 = 0.f;
    for (int j = tid; j < DD; j += 256) { float v = x[j]; s += v; s2 += v*v; }
    rs[tid] = s; rs2[tid] = s2;
    __syncthreads();
    for (int o = 128; o > 0; o >>= 1) {
        if (tid < o) { rs[tid] += rs[tid+o]; rs2[tid] += rs2[tid+o]; }
        __syncthreads();
    }
    const float m    = rs[0] * (1.f/DD);
    const float var  = rs2[0] * (1.f/DD) - m*m;
    const float rstd = rsqrtf(var + EPSF);
    float* y = Y + (size_t)row * DD;
    for (int j = tid; j < DD; j += 256)
        y[j] = (x[j] - m) * rstd * g[j] + b[j];
}

// ---------------- attention kernel 1: per-chunk K^T V [64x64] --------------
__global__ void attn_kvc_kernel(const float* __restrict__ Kx, const float* __restrict__ Vx,
                                float* __restrict__ kvc)
{
    __shared__ float ks[64][68], vs[64][68];
    const int blk = blockIdx.x;          // bh*NC + c
    const int bh  = blk >> 4, c = blk & 15;
    const int b   = bh >> 3,  h = bh & 7;
    const int tid = threadIdx.x;
    const int j   = tid >> 2, base = (tid & 3) * 16;

    const size_t tok = (size_t)(b*SS + c*64 + j) * DD + h*DKH + base;
#pragma unroll
    for (int u = 0; u < 4; ++u) {
        *(float4*)&ks[j][base + u*4] = *(const float4*)&Kx[tok + u*4];
        *(float4*)&vs[j][base + u*4] = *(const float4*)&Vx[tok + u*4];
    }
    __syncthreads();

    const int p = tid >> 2, qb = tid & 3;
    float acc[16] = {};
    for (int jj = 0; jj < 64; ++jj) {
        const float kp = ks[jj][p];
#pragma unroll
        for (int i = 0; i < 16; ++i) acc[i] += kp * vs[jj][qb + 4*i];
    }
    float* out = kvc + (size_t)blk * 4096 + p * 64;
#pragma unroll
    for (int i = 0; i < 16; ++i) out[qb + 4*i] = acc[i];
}

// ---------------- attention kernel 2: exclusive prefix over chunks ---------
__global__ void attn_prefix_kernel(const float* __restrict__ kvc, float* __restrict__ st)
{
    const int bh = blockIdx.x;
    const int tid = threadIdx.x;
    for (int r = 0; r < 16; ++r) {
        const int e = tid + r * 256;
        float run = 0.f;
        for (int c = 0; c < NC; ++c) {
            const size_t idx = ((size_t)bh*NC + c) * 4096 + e;
            st[idx] = run;
            run += kvc[idx];
        }
    }
}

// ---------------- attention kernel 3: O = tril(QK^T)V + Q*state ------------
__global__ void attn_out_kernel(const float* __restrict__ Qx, const float* __restrict__ Kx,
                                const float* __restrict__ Vx, const float* __restrict__ st,
                                float* __restrict__ Att)
{
    extern __shared__ float sm[];
    float (*qs )[68] = (float(*)[68])sm;
    float (*ks )[68] = qs  + 64;
    float (*vs )[68] = ks  + 64;
    float (*ssm)[68] = vs  + 64;
    float (*sts)[68] = ssm + 64;

    const int blk = blockIdx.x;
    const int bh  = blk >> 4, c = blk & 15;
    const int b   = bh >> 3,  h = bh & 7;
    const int tid = threadIdx.x;
    const int row = tid >> 2, base = (tid & 3) * 16;

    const size_t tok = (size_t)(b*SS + c*64 + row) * DD + h*DKH + base;
    const float* stg = st + (size_t)blk * 4096 + row * 64 + base;
#pragma unroll
    for (int u = 0; u < 4; ++u) {
        *(float4*)&qs [row][base + u*4] = *(const float4*)&Qx[tok + u*4];
        *(float4*)&ks [row][base + u*4] = *(const float4*)&Kx[tok + u*4];
        *(float4*)&vs [row][base + u*4] = *(const float4*)&Vx[tok + u*4];
        *(float4*)&sts[row][base + u*4] = *(const float4*)&stg[u*4];
    }
    __syncthreads();

    const int i = tid >> 2, j0 = tid & 3;
    // scores with causal mask (j <= i, diagonal included)
    for (int jj = 0; jj < 16; ++jj) {
        const int j = j0 + 4*jj;
        float d = 0.f;
#pragma unroll
        for (int p = 0; p < 64; ++p) d += qs[i][p] * ks[j][p];
        ssm[i][j] = (j <= i) ? d : 0.f;
    }
    __syncthreads();

    float acc[16] = {};
    for (int jj = 0; jj < 64; ++jj) {
        const float sij = ssm[i][jj];
        const float qip = qs[i][jj];
#pragma unroll
        for (int dd = 0; dd < 16; ++dd) {
            acc[dd] += sij * vs[jj][j0 + 4*dd];
            acc[dd] += qip * sts[jj][j0 + 4*dd];
        }
    }
    float* outp = Att + (size_t)(b*SS + c*64 + i) * DD + h*DKH;
#pragma unroll
    for (int dd = 0; dd < 16; ++dd) outp[j0 + 4*dd] = acc[dd];
}

// ---------------------------------------------------------------------------
extern "C" void kernel_launch(void* const* d_in, const int* in_sizes, int n_in,
                              void* d_out, int out_size)
{
    const float* src = (const float*)d_in[0];
    const float* Wq  = (const float*)d_in[1];
    const float* bq  = (const float*)d_in[2];
    const float* Wk  = (const float*)d_in[3];
    const float* bk  = (const float*)d_in[4];
    const float* Wv  = (const float*)d_in[5];
    const float* bv  = (const float*)d_in[6];
    const float* Wo  = (const float*)d_in[7];
    const float* bo  = (const float*)d_in[8];
    const float* W1  = (const float*)d_in[9];
    const float* b1  = (const float*)d_in[10];
    const float* W2  = (const float*)d_in[11];
    const float* b2  = (const float*)d_in[12];
    const float* g1  = (const float*)d_in[13];
    const float* be1 = (const float*)d_in[14];
    const float* g2  = (const float*)d_in[15];
    const float* be2 = (const float*)d_in[16];
    const float* gf  = (const float*)d_in[17];
    const float* bef = (const float*)d_in[18];
    float* out = (float*)d_out;

    float *px, *pq, *pk, *pv, *patt, *ptmp, *pff, *pkvc, *pst;
    cudaGetSymbolAddress((void**)&px,   g_x);
    cudaGetSymbolAddress((void**)&pq,   g_q);
    cudaGetSymbolAddress((void**)&pk,   g_k);
    cudaGetSymbolAddress((void**)&pv,   g_v);
    cudaGetSymbolAddress((void**)&patt, g_att);
    cudaGetSymbolAddress((void**)&ptmp, g_tmp);
    cudaGetSymbolAddress((void**)&pff,  g_ff);
    cudaGetSymbolAddress((void**)&pkvc, g_kvc);
    cudaGetSymbolAddress((void**)&pst,  g_st);

    static const int ATTN_SMEM = 5 * 64 * 68 * 4;  // 87,040 B
    cudaFuncSetAttribute(attn_out_kernel, cudaFuncAttributeMaxDynamicSharedMemorySize, ATTN_SMEM);

    // x = src
    cudaMemcpyAsync(px, src, (size_t)NTOK * DD * sizeof(float), cudaMemcpyDeviceToDevice, 0);

    const dim3 gD (DD  / 64, NTOK / 64);   // N=512 GEMMs
    const dim3 gDF(DFF / 64, NTOK / 64);   // N=2048 GEMM
    const dim3 blk(256);

    for (int i = 0; i < LL; ++i) {
        const float* wq = Wq + (size_t)i*DD*DD;  const float* bqv = bq + (size_t)i*DD;
        const float* wk = Wk + (size_t)i*DD*DD;  const float* bkv = bk + (size_t)i*DD;
        const float* wv = Wv + (size_t)i*DD*DD;  const float* bvv = bv + (size_t)i*DD;
        const float* wo = Wo + (size_t)i*DD*DD;  const float* bov = bo + (size_t)i*DD;
        const float* w1 = W1 + (size_t)i*DD*DFF; const float* b1v = b1 + (size_t)i*DFF;
        const float* w2 = W2 + (size_t)i*DFF*DD; const float* b2v = b2 + (size_t)i*DD;

        // Q/K/V projections (token-major [N,D] layout)
        sgemm_kernel<0><<<gD, blk>>>(px, wq, bqv, nullptr, pq, NTOK, DD, DD);
        sgemm_kernel<0><<<gD, blk>>>(px, wk, bkv, nullptr, pk, NTOK, DD, DD);
        sgemm_kernel<0><<<gD, blk>>>(px, wv, bvv, nullptr, pv, NTOK, DD, DD);

        // chunked causal linear attention
        attn_kvc_kernel   <<<BH*NC, blk>>>(pk, pv, pkvc);
        attn_prefix_kernel<<<BH,    blk>>>(pkvc, pst);
        attn_out_kernel   <<<BH*NC, blk, ATTN_SMEM>>>(pq, pk, pv, pst, patt);

        // out proj + residual, then LN1
        sgemm_kernel<2><<<gD, blk>>>(patt, wo, bov, px, ptmp, NTOK, DD, DD);
        ln_kernel<<<NTOK, blk>>>(ptmp, g1 + (size_t)i*DD, be1 + (size_t)i*DD, px);

        // FFN
        sgemm_kernel<1><<<gDF, blk>>>(px,  w1, b1v, nullptr, pff, NTOK, DFF, DD);
        sgemm_kernel<2><<<gD,  blk>>>(pff, w2, b2v, px,     ptmp, NTOK, DD, DFF);
        ln_kernel<<<NTOK, blk>>>(ptmp, g2 + (size_t)i*DD, be2 + (size_t)i*DD, px);
    }

    // final encoder LayerNorm -> output
    ln_kernel<<<NTOK, blk>>>(px, gf, bef, out);
}

// round 5
// speedup vs baseline: 1.6343x; 1.6343x over previous
#include <cuda_runtime.h>
#include <cuda_bf16.h>
#include <cstdint>
#include <cstddef>

#define BB   2
#define SS   1024
#define LL   2
#define HH   8
#define DD   512
#define DFF  2048
#define DKH  64
#define NTOK (BB*SS)      // 2048
#define NC   (SS/64)      // 16
#define BH   (BB*HH)      // 16
#define QSTR 1536
#define EPSF 1e-5f

typedef __nv_bfloat16 bf16;

// ---------------- scratch (device globals; no allocation) ----------------
__device__ __align__(128) float g_x   [NTOK*DD];    // residual stream fp32
__device__ __align__(128) float g_tmp [NTOK*DD];
__device__ __align__(128) float g_qkv [NTOK*QSTR];  // fused q|k|v fp32
__device__ __align__(128) float g_kvc [BH*NC*DKH*DKH];
__device__ __align__(128) float g_st  [BH*NC*DKH*DKH];
__device__ __align__(128) bf16  g_xh  [NTOK*DD];
__device__ __align__(128) bf16  g_xl  [NTOK*DD];
__device__ __align__(128) bf16  g_atth[NTOK*DD];
__device__ __align__(128) bf16  g_attl[NTOK*DD];
__device__ __align__(128) bf16  g_ffh [NTOK*DFF];
__device__ __align__(128) bf16  g_ffl [NTOK*DFF];
// transposed+split weights per layer: qkv [1536,512] | o [512,512] | w1 [2048,512] | w2 [512,2048]
#define WT_QKV 0
#define WT_O   (QSTR*DD)                 // 786432
#define WT_1   (WT_O + DD*DD)            // 1048576
#define WT_2   (WT_1 + DFF*DD)           // 2097152
#define WT_LAYER (WT_2 + DD*DFF)         // 3145728
__device__ __align__(128) bf16  g_wth [LL*WT_LAYER];
__device__ __align__(128) bf16  g_wtl [LL*WT_LAYER];
__device__ __align__(128) float g_bqkv[LL*QSTR];

// ============================ helpers ==================================
__device__ __forceinline__ void split_bf16(float v, bf16& h, bf16& l){
    h = __float2bfloat16(v);
    l = __float2bfloat16(v - __bfloat162float(h));
}
// smem tile: 128 rows x 32 bf16 cols = 64B/row; 16B groups XOR-swizzled
__device__ __forceinline__ int swz(int r, int c){
    return r*64 + ((((c >> 3) ^ ((r >> 1) & 3)) << 4)) + ((c & 7) << 1);
}
__device__ __forceinline__ void mma_bf16(float* d, const uint32_t* a, const uint32_t* b){
    asm volatile(
        "mma.sync.aligned.m16n8k16.row.col.f32.bf16.bf16.f32 "
        "{%0,%1,%2,%3}, {%4,%5,%6,%7}, {%8,%9}, {%0,%1,%2,%3};\n"
        : "+f"(d[0]), "+f"(d[1]), "+f"(d[2]), "+f"(d[3])
        : "r"(a[0]), "r"(a[1]), "r"(a[2]), "r"(a[3]), "r"(b[0]), "r"(b[1]));
}

// ============== bf16 3-term GEMM: C[M,N] = A[M,K] @ B^T ====================
// A?,B?: bf16 [rows,K] row-major (hi/lo split). 3 passes: AhBh + AlBh + AhBl.
// EPI: 0 = +bias -> fp32 C;  1 = +bias,relu -> split bf16 Ch/Cl;  2 = +bias+R -> fp32 C
template<int EPI>
__global__ void __launch_bounds__(256, 1)
bf16_gemm(const bf16* __restrict__ Ah, const bf16* __restrict__ Al,
          const bf16* __restrict__ Bh, const bf16* __restrict__ Bl,
          const float* __restrict__ bias, const float* __restrict__ R,
          float* __restrict__ C, bf16* __restrict__ Ch, bf16* __restrict__ Cl,
          int M, int N, int K)
{
    __shared__ __align__(16) char smem[2*4*8192];   // 2 bufs x (Ah,Al,Bh,Bl) 8KB tiles
    const int tid  = threadIdx.x, lane = tid & 31, wid = tid >> 5;
    const int wm   = (wid >> 2) * 64, wn = (wid & 3) * 32;
    const int m0   = blockIdx.y * 128, n0 = blockIdx.x * 128;

    float acc[4][4][4] = {};
    uint4 rA0[2], rA1[2], rB0[2], rB1[2];

    const int lr0 = tid >> 2, lkg = tid & 3;
    const int nch = K >> 5;

    // chunk loaders (LDG -> regs, regs -> swizzled STS)
    auto ldg_chunk = [&](int ch){
#pragma unroll
        for (int it = 0; it < 2; ++it){
            const int row = lr0 + it * 64;
            const size_t oA = (size_t)(m0 + row) * K + ch * 32 + lkg * 8;
            const size_t oB = (size_t)(n0 + row) * K + ch * 32 + lkg * 8;
            rA0[it] = *(const uint4*)(Ah + oA);
            rA1[it] = *(const uint4*)(Al + oA);
            rB0[it] = *(const uint4*)(Bh + oB);
            rB1[it] = *(const uint4*)(Bl + oB);
        }
    };
    auto sts_chunk = [&](int buf){
        char* b = smem + buf * 32768;
#pragma unroll
        for (int it = 0; it < 2; ++it){
            const int row = lr0 + it * 64;
            const int off = row * 64 + (((lkg ^ ((row >> 1) & 3))) << 4);
            *(uint4*)(b +         off) = rA0[it];
            *(uint4*)(b +  8192 + off) = rA1[it];
            *(uint4*)(b + 16384 + off) = rB0[it];
            *(uint4*)(b + 24576 + off) = rB1[it];
        }
    };

    ldg_chunk(0); sts_chunk(0); __syncthreads();

    for (int ch = 0; ch < nch; ++ch){
        if (ch + 1 < nch) ldg_chunk(ch + 1);
        const char* b    = smem + (ch & 1) * 32768;
        const char* AsH  = b;
        const char* AsL  = b + 8192;
        const char* BsH  = b + 16384;
        const char* BsL  = b + 24576;

#pragma unroll
        for (int ks = 0; ks < 2; ++ks){
            uint32_t bh[4][2], bl[4][2];
#pragma unroll
            for (int nt = 0; nt < 4; ++nt){
                const int n = wn + nt * 8 + (lane >> 2);
                const int c = ks * 16 + (lane & 3) * 2;
                const int o0 = swz(n, c), o1 = swz(n, c + 8);
                bh[nt][0] = *(const uint32_t*)(BsH + o0);
                bh[nt][1] = *(const uint32_t*)(BsH + o1);
                bl[nt][0] = *(const uint32_t*)(BsL + o0);
                bl[nt][1] = *(const uint32_t*)(BsL + o1);
            }
#pragma unroll
            for (int mt = 0; mt < 4; ++mt){
                const int r = wm + mt * 16 + (lane >> 2);
                const int c = ks * 16 + (lane & 3) * 2;
                const int o00 = swz(r, c),     o10 = swz(r + 8, c);
                const int o01 = swz(r, c + 8), o11 = swz(r + 8, c + 8);
                uint32_t ah[4], al[4];
                ah[0] = *(const uint32_t*)(AsH + o00);
                ah[1] = *(const uint32_t*)(AsH + o10);
                ah[2] = *(const uint32_t*)(AsH + o01);
                ah[3] = *(const uint32_t*)(AsH + o11);
                al[0] = *(const uint32_t*)(AsL + o00);
                al[1] = *(const uint32_t*)(AsL + o10);
                al[2] = *(const uint32_t*)(AsL + o01);
                al[3] = *(const uint32_t*)(AsL + o11);
#pragma unroll
                for (int nt = 0; nt < 4; ++nt){
                    mma_bf16(acc[mt][nt], ah, bh[nt]);
                    mma_bf16(acc[mt][nt], al, bh[nt]);
                    mma_bf16(acc[mt][nt], ah, bl[nt]);
                }
            }
        }
        if (ch + 1 < nch){ sts_chunk((ch + 1) & 1); __syncthreads(); }
    }

    // epilogue: direct from accumulator fragments
#pragma unroll
    for (int mt = 0; mt < 4; ++mt){
#pragma unroll
        for (int nt = 0; nt < 4; ++nt){
            const int col = n0 + wn + nt * 8 + (lane & 3) * 2;
            const float b0 = bias[col], b1 = bias[col + 1];
#pragma unroll
            for (int hf = 0; hf < 2; ++hf){
                const int row = m0 + wm + mt * 16 + (lane >> 2) + hf * 8;
                float v0 = acc[mt][nt][hf * 2 + 0] + b0;
                float v1 = acc[mt][nt][hf * 2 + 1] + b1;
                const size_t o = (size_t)row * N + col;
                if (EPI == 0){
                    *(float2*)&C[o] = make_float2(v0, v1);
                } else if (EPI == 1){
                    v0 = fmaxf(v0, 0.f); v1 = fmaxf(v1, 0.f);
                    bf16 h0, l0, h1, l1;
                    split_bf16(v0, h0, l0); split_bf16(v1, h1, l1);
                    *(__nv_bfloat162*)&Ch[o] = __nv_bfloat162(h0, h1);
                    *(__nv_bfloat162*)&Cl[o] = __nv_bfloat162(l0, l1);
                } else {
                    const float2 rr = *(const float2*)&R[o];
                    *(float2*)&C[o] = make_float2(v0 + rr.x, v1 + rr.y);
                }
            }
        }
    }
}

// ---------------- weight transpose + split: D[n,k] = split(S[k,n]) ---------
__global__ void transpose_split(const float* __restrict__ S, bf16* __restrict__ Dh,
                                bf16* __restrict__ Dl, int K, int N)
{
    __shared__ float t[32][33];
    const int k0 = blockIdx.y * 32, n0 = blockIdx.x * 32;
    const int x = threadIdx.x, y = threadIdx.y;  // 32 x 8
#pragma unroll
    for (int i = 0; i < 32; i += 8)
        t[y + i][x] = S[(size_t)(k0 + y + i) * N + n0 + x];
    __syncthreads();
#pragma unroll
    for (int i = 0; i < 32; i += 8){
        const float v = t[x][y + i];
        bf16 h, l; split_bf16(v, h, l);
        const size_t o = (size_t)(n0 + y + i) * K + k0 + x;
        Dh[o] = h; Dl[o] = l;
    }
}

// ---------------- split fp32 -> bf16 hi/lo ---------------------------------
__global__ void split_kernel(const float* __restrict__ X, bf16* __restrict__ Xh,
                             bf16* __restrict__ Xl)
{
    const int t = blockIdx.x * 256 + threadIdx.x;
    const float4 v = ((const float4*)X)[t];
    bf16 h0,l0,h1,l1,h2,l2,h3,l3;
    split_bf16(v.x,h0,l0); split_bf16(v.y,h1,l1);
    split_bf16(v.z,h2,l2); split_bf16(v.w,h3,l3);
    ((__nv_bfloat162*)Xh)[t*2+0] = __nv_bfloat162(h0,h1);
    ((__nv_bfloat162*)Xh)[t*2+1] = __nv_bfloat162(h2,h3);
    ((__nv_bfloat162*)Xl)[t*2+0] = __nv_bfloat162(l0,l1);
    ((__nv_bfloat162*)Xl)[t*2+1] = __nv_bfloat162(l2,l3);
}

__global__ void concat_bias(const float* __restrict__ bq, const float* __restrict__ bk,
                            const float* __restrict__ bv, float* __restrict__ dst)
{
    const int t = blockIdx.x * 256 + threadIdx.x;
    if (t < 512)       dst[t] = bq[t];
    else if (t < 1024) dst[t] = bk[t - 512];
    else if (t < 1536) dst[t] = bv[t - 1024];
}

// ---------------- LayerNorm (+ optional bf16 split outputs) ----------------
__global__ void ln_kernel(const float* __restrict__ X, const float* __restrict__ g,
                          const float* __restrict__ b, float* __restrict__ Y,
                          bf16* __restrict__ Yh, bf16* __restrict__ Yl)
{
    const int row = blockIdx.x;
    const int tid = threadIdx.x;
    const float* x = X + (size_t)row * DD;
    __shared__ float rs[256], rs2[256];
    float s = 0.f, s2 = 0.f;
    for (int j = tid; j < DD; j += 256) { float v = x[j]; s += v; s2 += v*v; }
    rs[tid] = s; rs2[tid] = s2;
    __syncthreads();
    for (int o = 128; o > 0; o >>= 1) {
        if (tid < o) { rs[tid] += rs[tid+o]; rs2[tid] += rs2[tid+o]; }
        __syncthreads();
    }
    const float m    = rs[0] * (1.f/DD);
    const float var  = rs2[0] * (1.f/DD) - m*m;
    const float rstd = rsqrtf(var + EPSF);
    for (int j = tid; j < DD; j += 256){
        const float v = (x[j] - m) * rstd * g[j] + b[j];
        Y[(size_t)row * DD + j] = v;
        if (Yh){
            bf16 h, l; split_bf16(v, h, l);
            Yh[(size_t)row * DD + j] = h;
            Yl[(size_t)row * DD + j] = l;
        }
    }
}

// ---------------- attention kernel 1: per-chunk K^T V [64x64] --------------
__global__ void attn_kvc_kernel(const float* __restrict__ QKV, float* __restrict__ kvc)
{
    __shared__ float ks[64][68], vs[64][68];
    const int blk = blockIdx.x;          // bh*NC + c
    const int bh  = blk >> 4, c = blk & 15;
    const int b   = bh >> 3,  h = bh & 7;
    const int tid = threadIdx.x;
    const int j   = tid >> 2, base = (tid & 3) * 16;

    const size_t tok = (size_t)(b*SS + c*64 + j) * QSTR + h*DKH + base;
    const float* Kx = QKV + DD;
    const float* Vx = QKV + 2*DD;
#pragma unroll
    for (int u = 0; u < 4; ++u) {
        *(float4*)&ks[j][base + u*4] = *(const float4*)&Kx[tok + u*4];
        *(float4*)&vs[j][base + u*4] = *(const float4*)&Vx[tok + u*4];
    }
    __syncthreads();

    const int p = tid >> 2, qb = tid & 3;
    float acc[16] = {};
    for (int jj = 0; jj < 64; ++jj) {
        const float kp = ks[jj][p];
#pragma unroll
        for (int i = 0; i < 16; ++i) acc[i] += kp * vs[jj][qb + 4*i];
    }
    float* out = kvc + (size_t)blk * 4096 + p * 64;
#pragma unroll
    for (int i = 0; i < 16; ++i) out[qb + 4*i] = acc[i];
}

// ---------------- attention kernel 2: exclusive prefix over chunks ---------
__global__ void attn_prefix_kernel(const float* __restrict__ kvc, float* __restrict__ st)
{
    const int bh = blockIdx.x >> 4, r = blockIdx.x & 15;
    const int e  = threadIdx.x + r * 256;
    const size_t base = (size_t)bh * NC * 4096 + e;
    float v[NC];
#pragma unroll
    for (int c = 0; c < NC; ++c) v[c] = kvc[base + (size_t)c * 4096];
    float run = 0.f;
#pragma unroll
    for (int c = 0; c < NC; ++c) { st[base + (size_t)c * 4096] = run; run += v[c]; }
}

// ---------------- attention kernel 3: O = tril(QK^T)V + Q*state ------------
// writes split bf16 output for the Wo GEMM
__global__ void attn_out_kernel(const float* __restrict__ QKV, const float* __restrict__ st,
                                bf16* __restrict__ Ath, bf16* __restrict__ Atl)
{
    extern __shared__ float sm[];
    float (*qs )[68] = (float(*)[68])sm;
    float (*ks )[68] = qs  + 64;
    float (*vs )[68] = ks  + 64;
    float (*ssm)[68] = vs  + 64;
    float (*sts)[68] = ssm + 64;

    const int blk = blockIdx.x;
    const int bh  = blk >> 4, c = blk & 15;
    const int b   = bh >> 3,  h = bh & 7;
    const int tid = threadIdx.x;
    const int row = tid >> 2, base = (tid & 3) * 16;

    const size_t tok = (size_t)(b*SS + c*64 + row) * QSTR + h*DKH + base;
    const float* stg = st + (size_t)blk * 4096 + row * 64 + base;
#pragma unroll
    for (int u = 0; u < 4; ++u) {
        *(float4*)&qs [row][base + u*4] = *(const float4*)&QKV[tok + u*4];
        *(float4*)&ks [row][base + u*4] = *(const float4*)&QKV[tok + DD + u*4];
        *(float4*)&vs [row][base + u*4] = *(const float4*)&QKV[tok + 2*DD + u*4];
        *(float4*)&sts[row][base + u*4] = *(const float4*)&stg[u*4];
    }
    __syncthreads();

    const int i = tid >> 2, j0 = tid & 3;
    for (int jj = 0; jj < 16; ++jj) {
        const int j = j0 + 4*jj;
        float d = 0.f;
#pragma unroll
        for (int p = 0; p < 64; ++p) d += qs[i][p] * ks[j][p];
        ssm[i][j] = (j <= i) ? d : 0.f;
    }
    __syncthreads();

    float acc[16] = {};
    for (int jj = 0; jj < 64; ++jj) {
        const float sij = ssm[i][jj];
        const float qip = qs[i][jj];
#pragma unroll
        for (int dd = 0; dd < 16; ++dd) {
            acc[dd] += sij * vs[jj][j0 + 4*dd];
            acc[dd] += qip * sts[jj][j0 + 4*dd];
        }
    }
    const size_t outp = (size_t)(b*SS + c*64 + i) * DD + h*DKH;
#pragma unroll
    for (int dd = 0; dd < 16; ++dd){
        bf16 h2, l2; split_bf16(acc[dd], h2, l2);
        Ath[outp + j0 + 4*dd] = h2;
        Atl[outp + j0 + 4*dd] = l2;
    }
}

// ---------------------------------------------------------------------------
extern "C" void kernel_launch(void* const* d_in, const int* in_sizes, int n_in,
                              void* d_out, int out_size)
{
    const float* src = (const float*)d_in[0];
    const float* Wq  = (const float*)d_in[1];
    const float* bq  = (const float*)d_in[2];
    const float* Wk  = (const float*)d_in[3];
    const float* bk  = (const float*)d_in[4];
    const float* Wv  = (const float*)d_in[5];
    const float* bv  = (const float*)d_in[6];
    const float* Wo  = (const float*)d_in[7];
    const float* bo  = (const float*)d_in[8];
    const float* W1  = (const float*)d_in[9];
    const float* b1  = (const float*)d_in[10];
    const float* W2  = (const float*)d_in[11];
    const float* b2  = (const float*)d_in[12];
    const float* g1  = (const float*)d_in[13];
    const float* be1 = (const float*)d_in[14];
    const float* g2  = (const float*)d_in[15];
    const float* be2 = (const float*)d_in[16];
    const float* gf  = (const float*)d_in[17];
    const float* bef = (const float*)d_in[18];
    float* out = (float*)d_out;

    float *px, *ptmp, *pqkv, *pkvc, *pst, *pbqkv;
    bf16 *pxh, *pxl, *path, *patl, *pffh, *pffl, *pwth, *pwtl;
    cudaGetSymbolAddress((void**)&px,    g_x);
    cudaGetSymbolAddress((void**)&ptmp,  g_tmp);
    cudaGetSymbolAddress((void**)&pqkv,  g_qkv);
    cudaGetSymbolAddress((void**)&pkvc,  g_kvc);
    cudaGetSymbolAddress((void**)&pst,   g_st);
    cudaGetSymbolAddress((void**)&pbqkv, g_bqkv);
    cudaGetSymbolAddress((void**)&pxh,   g_xh);
    cudaGetSymbolAddress((void**)&pxl,   g_xl);
    cudaGetSymbolAddress((void**)&path,  g_atth);
    cudaGetSymbolAddress((void**)&patl,  g_attl);
    cudaGetSymbolAddress((void**)&pffh,  g_ffh);
    cudaGetSymbolAddress((void**)&pffl,  g_ffl);
    cudaGetSymbolAddress((void**)&pwth,  g_wth);
    cudaGetSymbolAddress((void**)&pwtl,  g_wtl);

    static const int ATTN_SMEM = 5 * 64 * 68 * 4;  // 87,040 B
    cudaFuncSetAttribute(attn_out_kernel, cudaFuncAttributeMaxDynamicSharedMemorySize, ATTN_SMEM);

    // x = src (residual); split src for QKV GEMM
    cudaMemcpyAsync(px, src, (size_t)NTOK * DD * sizeof(float), cudaMemcpyDeviceToDevice, 0);
    split_kernel<<<NTOK*DD/4/256, 256>>>(src, pxh, pxl);

    const dim3 tb(32, 8);
    for (int i = 0; i < LL; ++i) {
        bf16* wh = pwth + (size_t)i * WT_LAYER;
        bf16* wl = pwtl + (size_t)i * WT_LAYER;
        // QKV fused: rows 0-511 = q, 512-1023 = k, 1024-1535 = v  (each [512,512])
        transpose_split<<<dim3(DD/32,  DD/32),  tb>>>(Wq + (size_t)i*DD*DD,  wh + WT_QKV,            wl + WT_QKV,            DD,  DD);
        transpose_split<<<dim3(DD/32,  DD/32),  tb>>>(Wk + (size_t)i*DD*DD,  wh + WT_QKV + DD*DD,    wl + WT_QKV + DD*DD,    DD,  DD);
        transpose_split<<<dim3(DD/32,  DD/32),  tb>>>(Wv + (size_t)i*DD*DD,  wh + WT_QKV + 2*DD*DD,  wl + WT_QKV + 2*DD*DD,  DD,  DD);
        transpose_split<<<dim3(DD/32,  DD/32),  tb>>>(Wo + (size_t)i*DD*DD,  wh + WT_O,              wl + WT_O,              DD,  DD);
        transpose_split<<<dim3(DFF/32, DD/32),  tb>>>(W1 + (size_t)i*DD*DFF, wh + WT_1,              wl + WT_1,              DD,  DFF);
        transpose_split<<<dim3(DD/32,  DFF/32), tb>>>(W2 + (size_t)i*DFF*DD, wh + WT_2,              wl + WT_2,              DFF, DD);
        concat_bias<<<6, 256>>>(bq + (size_t)i*DD, bk + (size_t)i*DD, bv + (size_t)i*DD, pbqkv + (size_t)i*QSTR);
    }

    const dim3 gQKV(QSTR / 128, NTOK / 128);   // 12 x 16
    const dim3 gD  (DD   / 128, NTOK / 128);   // 4 x 16
    const dim3 gDF (DFF  / 128, NTOK / 128);   // 16 x 16
    const dim3 blk(256);

    for (int i = 0; i < LL; ++i) {
        bf16* wh = pwth + (size_t)i * WT_LAYER;
        bf16* wl = pwtl + (size_t)i * WT_LAYER;
        const float* bov = bo + (size_t)i*DD;
        const float* b1v = b1 + (size_t)i*DFF;
        const float* b2v = b2 + (size_t)i*DD;

        // fused QKV projection -> g_qkv fp32 [NTOK,1536]
        bf16_gemm<0><<<gQKV, 256>>>(pxh, pxl, wh + WT_QKV, wl + WT_QKV,
                                    pbqkv + (size_t)i*QSTR, nullptr,
                                    pqkv, nullptr, nullptr, NTOK, QSTR, DD);

        // chunked causal linear attention -> split bf16 att
        attn_kvc_kernel   <<<BH*NC, blk>>>(pqkv, pkvc);
        attn_prefix_kernel<<<BH*16, blk>>>(pkvc, pst);
        attn_out_kernel   <<<BH*NC, blk, ATTN_SMEM>>>(pqkv, pst, path, patl);

        // out proj + residual -> LN1 (LN emits fp32 + split)
        bf16_gemm<2><<<gD, 256>>>(path, patl, wh + WT_O, wl + WT_O,
                                  bov, px, ptmp, nullptr, nullptr, NTOK, DD, DD);
        ln_kernel<<<NTOK, blk>>>(ptmp, g1 + (size_t)i*DD, be1 + (size_t)i*DD, px, pxh, pxl);

        // FFN: FF1 emits split bf16 directly; FF2 adds residual
        bf16_gemm<1><<<gDF, 256>>>(pxh, pxl, wh + WT_1, wl + WT_1,
                                   b1v, nullptr, nullptr, pffh, pffl, NTOK, DFF, DD);
        bf16_gemm<2><<<gD, 256>>>(pffh, pffl, wh + WT_2, wl + WT_2,
                                  b2v, px, ptmp, nullptr, nullptr, NTOK, DD, DFF);
        ln_kernel<<<NTOK, blk>>>(ptmp, g2 + (size_t)i*DD, be2 + (size_t)i*DD, px, pxh, pxl);
    }

    // final encoder LayerNorm -> output
    ln_kernel<<<NTOK, blk>>>(px, gf, bef, out, nullptr, nullptr);
}